// round 8
// baseline (speedup 1.0000x reference)
#include <cuda_runtime.h>
#include <cstdint>

#define TSTEPS 60
#define NGROUPS 8192            // 32768 batches / 4 per group
typedef unsigned long long u64;

__device__ __forceinline__ u64 pk(float a, float b) {
    u64 r; asm("mov.b64 %0, {%1, %2};" : "=l"(r) : "f"(a), "f"(b)); return r;
}
__device__ __forceinline__ void upk(u64 v, float& a, float& b) {
    asm("mov.b64 {%0, %1}, %2;" : "=f"(a), "=f"(b) : "l"(v));
}
__device__ __forceinline__ float lof(u64 v) { float a, b; upk(v, a, b); return a; }
__device__ __forceinline__ float hif(u64 v) { float a, b; upk(v, a, b); return b; }
__device__ __forceinline__ void ffma2_ip(u64& acc, u64 a, u64 b) {
    asm("fma.rn.f32x2 %0, %1, %2, %0;" : "+l"(acc) : "l"(a), "l"(b));
}
__device__ __forceinline__ float hadd(u64 v) { float a, b; upk(v, a, b); return a + b; }
__device__ __forceinline__ float sigmoidf_(float x) {
    return __fdividef(1.0f, 1.0f + __expf(-x));
}
__device__ __forceinline__ float tanhf_(float x) {
    return __fdividef(2.0f, 1.0f + __expf(-2.0f * x)) - 1.0f;
}

// Weight table: s_w[part][gateRow(72)][14 k-pair u64].
// part 0 = h-side (w_hh pairs, j=12 carries b_hh for n-rows), part 1 = x-side
// (w_ih pairs j<13, j=13 carries b_ih(+b_hh for r/z rows)). Activation pads are
// pk(1,0) in the matching slots so biases fall out of the same FFMA2 stream.
#define PSTRIDE 1010   // 72*14 + 2 u64 pad (bank de-phase between parts)

__global__ void __launch_bounds__(224, 1)
_ShotRNN_90417651516362_kernel(
    const float* __restrict__ x, const float* __restrict__ w_ih,
    const float* __restrict__ w_hh, const float* __restrict__ b_ih,
    const float* __restrict__ b_hh, const float* __restrict__ fc1_w,
    const float* __restrict__ fc1_b, const float* __restrict__ fc2_w,
    const float* __restrict__ fc2_b, float* __restrict__ out)
{
    __shared__ __align__(16) u64 s_w[2 * PSTRIDE];
    __shared__ __align__(16) float s_stage[7 * 832];   // 7 warps x 32 batches x 26
    __shared__ float s_fc[236];

    const int tid = threadIdx.x;

    for (int idx = tid; idx < 2 * 72 * 14; idx += 224) {
        int p = idx / (72 * 14), rem = idx - p * (72 * 14);
        int r2 = rem / 14, j = rem % 14;
        float a = 0.0f, b = 0.0f;
        if (p == 0) {
            if (j < 12) { a = w_hh[r2 * 24 + 2 * j]; b = w_hh[r2 * 24 + 2 * j + 1]; }
            else if (j == 12 && r2 >= 48) a = b_hh[r2];
        } else {
            if (j < 13) { a = w_ih[r2 * 26 + 2 * j]; b = w_ih[r2 * 26 + 2 * j + 1]; }
            else if (j == 13) a = (r2 < 48) ? (b_ih[r2] + b_hh[r2]) : b_ih[r2];
        }
        s_w[p * PSTRIDE + r2 * 14 + j] = pk(a, b);
    }
    for (int i = tid; i < 192; i += 224) s_fc[i] = fc1_w[i];
    if (tid < 8)  s_fc[192 + tid] = fc1_b[tid];
    if (tid < 32) s_fc[200 + tid] = fc2_w[tid];
    if (tid < 4)  s_fc[232 + tid] = fc2_b[tid];
    __syncthreads();

    const int lane = tid & 31, wl = tid >> 5;
    const int gidx = blockIdx.x * 7 + wl;          // global warp id
    const int g = lane & 7;                         // group within warp
    const int part = (lane >> 3) & 1;               // 0 = h-side, 1 = x-side
    const int rh = lane >> 4;                       // 0 = rows 0-11, 1 = rows 12-23
    const int group = gidx * 8 + g;
    const int grp = (group < NGROUPS) ? group : (NGROUPS - 1);
    float* stage = s_stage + wl * 832;
    const int warpB = gidx * 32;                    // warp's first batch index
    const u64* wbase = s_w + part * PSTRIDE;

    // ---- stage x(0): coalesced per-warp (13 float2 lanes per batch row) ----
#pragma unroll
    for (int b2 = 0; b2 < 32; b2++) {
        if (lane < 13) {
            int bb = warpB + b2; if (bb > 32767) bb = 32767;
            float2 v = __ldg((const float2*)(x + (size_t)bb * 1560) + lane);
            *(float2*)(stage + b2 * 26 + 2 * lane) = v;
        }
    }
    __syncwarp();

    // ---- activations: act[batch][14 k-pairs] ----
    u64 act[4][14];
    if (part == 0) {
#pragma unroll
        for (int b = 0; b < 4; b++) {
#pragma unroll
            for (int j = 0; j < 12; j++) act[b][j] = 0ull;
            act[b][12] = pk(1.0f, 0.0f);
            act[b][13] = 0ull;
        }
    } else {
#pragma unroll
        for (int b = 0; b < 4; b++) {
#pragma unroll
            for (int j = 0; j < 13; j++)
                act[b][j] = *(const u64*)(stage + (g * 4 + b) * 26 + 2 * j);
            act[b][13] = pk(1.0f, 0.0f);
        }
    }

#pragma unroll 1
    for (int t = 0; t < TSTEPS; t++) {
        const bool more = (t + 1 < TSTEPS);
        if (more) {   // prefetch x(t+1) into stage; consumed at end of this step
#pragma unroll
            for (int b2 = 0; b2 < 32; b2++) {
                if (lane < 13) {
                    int bb = warpB + b2; if (bb > 32767) bb = 32767;
                    float2 v = __ldg((const float2*)(x + (size_t)bb * 1560 + (t + 1) * 26) + lane);
                    *(float2*)(stage + b2 * 26 + 2 * lane) = v;
                }
            }
        }

        u64 outp[12];   // my 12 rows' new h, pk over my 2 epilogue batches
#pragma unroll
        for (int i = 0; i < 12; i++) {
            const int u = rh * 12 + i;   // global unit (runtime; SMEM index only)
            float sg[3][4];
#pragma unroll
            for (int g3 = 0; g3 < 3; g3++) {
                const ulonglong2* wp = (const ulonglong2*)(wbase + (g3 * 24 + u) * 14);
                u64 a0 = 0ull, a1 = 0ull, a2 = 0ull, a3 = 0ull;
#pragma unroll
                for (int jj = 0; jj < 7; jj++) {
                    ulonglong2 w = wp[jj];
                    ffma2_ip(a0, act[0][2*jj],   w.x);
                    ffma2_ip(a1, act[1][2*jj],   w.x);
                    ffma2_ip(a2, act[2][2*jj],   w.x);
                    ffma2_ip(a3, act[3][2*jj],   w.x);
                    ffma2_ip(a0, act[0][2*jj+1], w.y);
                    ffma2_ip(a1, act[1][2*jj+1], w.y);
                    ffma2_ip(a2, act[2][2*jj+1], w.y);
                    ffma2_ip(a3, act[3][2*jj+1], w.y);
                }
                sg[g3][0] = hadd(a0); sg[g3][1] = hadd(a1);
                sg[g3][2] = hadd(a2); sg[g3][3] = hadd(a3);
            }

            // h_old for this unit, all 4 batches (valid on part-0 lanes only)
            float ho[4];
#pragma unroll
            for (int b = 0; b < 4; b++) {
                u64 hp = rh ? act[b][6 + i / 2] : act[b][i / 2];
                ho[b] = (i & 1) ? hif(hp) : lof(hp);
            }

            u64 ex0 = pk(sg[0][0], sg[0][1]), ex1 = pk(sg[0][2], sg[0][3]);
            u64 ex2 = pk(sg[1][0], sg[1][1]), ex3 = pk(sg[1][2], sg[1][3]);
            u64 ex4 = pk(sg[2][0], sg[2][1]), ex5 = pk(sg[2][2], sg[2][3]);
            u64 ex6 = pk(ho[2], ho[3]);       // h-side -> x-side h_old transfer
            u64 rx0 = __shfl_xor_sync(0xffffffffu, ex0, 8);
            u64 rx1 = __shfl_xor_sync(0xffffffffu, ex1, 8);
            u64 rx2 = __shfl_xor_sync(0xffffffffu, ex2, 8);
            u64 rx3 = __shfl_xor_sync(0xffffffffu, ex3, 8);
            u64 rx4 = __shfl_xor_sync(0xffffffffu, ex4, 8);
            u64 rx5 = __shfl_xor_sync(0xffffffffu, ex5, 8);
            u64 rx6 = __shfl_xor_sync(0xffffffffu, ex6, 8);

            // My 2 epilogue batches: part0 -> b0,b1 ; part1 -> b2,b3
            u64 XR = part ? ex1 : rx0;
            u64 HR = part ? rx1 : ex0;
            u64 XZ = part ? ex3 : rx2;
            u64 HZ = part ? rx3 : ex2;
            u64 XN = part ? ex5 : rx4;
            u64 HN = part ? rx5 : ex4;
            u64 HO = part ? rx6 : pk(ho[0], ho[1]);

            float xr0, xr1, hr0, hr1, xz0, xz1, hz0, hz1, xn0, xn1, hn0, hn1, q0, q1;
            upk(XR, xr0, xr1); upk(HR, hr0, hr1);
            upk(XZ, xz0, xz1); upk(HZ, hz0, hz1);
            upk(XN, xn0, xn1); upk(HN, hn0, hn1);
            upk(HO, q0, q1);
            float rr0 = sigmoidf_(xr0 + hr0), rr1 = sigmoidf_(xr1 + hr1);
            float zz0 = sigmoidf_(xz0 + hz0), zz1 = sigmoidf_(xz1 + hz1);
            float nn0 = tanhf_(fmaf(rr0, hn0, xn0));
            float nn1 = tanhf_(fmaf(rr1, hn1, xn1));
            float o0 = fmaf(zz0, q0 - nn0, nn0);
            float o1 = fmaf(zz1, q1 - nn1, nn1);
            outp[i] = pk(o0, o1);
        }

        __syncwarp();   // stage(x(t+1)) visible before the x-side refill below

        // ---- gather new h across the 4 roles, rebuild activations ----
#pragma unroll
        for (int jj = 0; jj < 6; jj++) {
            u64 o0 = outp[2*jj], o1 = outp[2*jj+1];
            u64 p0 = __shfl_xor_sync(0xffffffffu, o0, 8);
            u64 p1 = __shfl_xor_sync(0xffffffffu, o1, 8);
            u64 q0 = __shfl_xor_sync(0xffffffffu, o0, 16);
            u64 q1 = __shfl_xor_sync(0xffffffffu, o1, 16);
            u64 s0 = __shfl_xor_sync(0xffffffffu, o0, 24);
            u64 s1 = __shfl_xor_sync(0xffffffffu, o1, 24);
            if (part == 0) {
                u64 e0 = rh ? q0 : o0, e1 = rh ? q1 : o1;   // rows 0-11, b01
                u64 f0 = rh ? s0 : p0, f1 = rh ? s1 : p1;   // rows 0-11, b23
                u64 g0 = rh ? o0 : q0, g1 = rh ? o1 : q1;   // rows 12-23, b01
                u64 h0 = rh ? p0 : s0, h1 = rh ? p1 : s1;   // rows 12-23, b23
                act[0][jj]     = pk(lof(e0), lof(e1));
                act[1][jj]     = pk(hif(e0), hif(e1));
                act[2][jj]     = pk(lof(f0), lof(f1));
                act[3][jj]     = pk(hif(f0), hif(f1));
                act[0][6 + jj] = pk(lof(g0), lof(g1));
                act[1][6 + jj] = pk(hif(g0), hif(g1));
                act[2][6 + jj] = pk(lof(h0), lof(h1));
                act[3][6 + jj] = pk(hif(h0), hif(h1));
            }
        }
        if (part == 1 && more) {   // x-side: refill activations with x(t+1)
#pragma unroll
            for (int b = 0; b < 4; b++)
#pragma unroll
                for (int j = 0; j < 13; j++)
                    act[b][j] = *(const u64*)(stage + (g * 4 + b) * 26 + 2 * j);
        }
    }

    // ---- FC head on part-0 lanes: (part0,rh0)->b0,b1 ; (part0,rh1)->b2,b3 ----
    if (part == 0 && group < NGROUPS) {
#pragma unroll
        for (int m = 0; m < 2; m++) {
            float hv[24];
#pragma unroll
            for (int j = 0; j < 12; j++) {
                u64 v = rh ? act[2 + m][j] : act[m][j];
                hv[2*j] = lof(v); hv[2*j+1] = hif(v);
            }
            float f1[8];
#pragma unroll
            for (int jy = 0; jy < 8; jy++) {
                float a = s_fc[192 + jy];
#pragma unroll
                for (int k = 0; k < 24; k++) a = fmaf(hv[k], s_fc[jy * 24 + k], a);
                f1[jy] = fmaxf(a, 0.0f);
            }
            float l[4];
#pragma unroll
            for (int c = 0; c < 4; c++) {
                float a = s_fc[232 + c];
#pragma unroll
                for (int k = 0; k < 8; k++) a = fmaf(f1[k], s_fc[200 + c * 8 + k], a);
                l[c] = a;
            }
            float mx = fmaxf(fmaxf(l[0], l[1]), fmaxf(l[2], l[3]));
            float e0 = __expf(l[0]-mx), e1 = __expf(l[1]-mx);
            float e2 = __expf(l[2]-mx), e3 = __expf(l[3]-mx);
            float inv = __fdividef(1.0f, e0 + e1 + e2 + e3);
            int batch = grp * 4 + rh * 2 + m;
            *(float4*)(out + (size_t)batch * 4) =
                make_float4(e0 * inv, e1 * inv, e2 * inv, e3 * inv);
        }
    }
}

extern "C" void kernel_launch(void* const* d_in, const int* in_sizes, int n_in,
                              void* d_out, int out_size) {
    // 147 CTAs x 224 threads = 1029 warps; 8 groups/warp, 4 batches/group.
    _ShotRNN_90417651516362_kernel<<<147, 224>>>(
        (const float*)d_in[0], (const float*)d_in[1], (const float*)d_in[2],
        (const float*)d_in[3], (const float*)d_in[4], (const float*)d_in[5],
        (const float*)d_in[6], (const float*)d_in[7], (const float*)d_in[8],
        (float*)d_out);
}